// round 2
// baseline (speedup 1.0000x reference)
#include <cuda_runtime.h>

#define B_   2
#define S_   2048
#define D_   1024
#define H_   16
#define HD_  64
#define BH_  (B_*H_)      // 32
#define M_   (B_*S_)      // 4096

// ------------------- scratch (device globals; no allocation) -------------------
__device__ float g_Q  [BH_*S_*HD_];
__device__ float g_Qd [BH_*S_*HD_];
__device__ float g_K  [BH_*S_*HD_];
__device__ float g_Kd [BH_*S_*HD_];
__device__ float g_V  [BH_*S_*HD_];
__device__ float g_defw[BH_*S_];
__device__ float g_att[M_*D_];

// =====================================================================
// SGEMM: C = A @ W^T.  A: [M_, D_] row-major, W: [1024, D_] row-major.
// 128x128 block tile, 8x8 per thread, BK=8, 256 threads.
// MODE 0: scatter C[m, n] -> out[(b*H + h)*S + s][hd]   (b=m/S, s=m%S, h=n/64, hd=n%64)
// MODE 1: linear  C[m*D_ + n]
// =====================================================================
template<int MODE>
__global__ __launch_bounds__(256, 2)
void gemm_kernel(const float* __restrict__ A,
                 const float* __restrict__ W,
                 float* __restrict__ C)
{
    __shared__ float As[8][128];
    __shared__ float Bs[8][128];

    const int tid = threadIdx.x;
    const int tx  = tid & 15;
    const int ty  = tid >> 4;
    const int m0  = blockIdx.y << 7;
    const int n0  = blockIdx.x << 7;

    const int lr = tid >> 1;          // 0..127
    const int lk = (tid & 1) << 2;    // 0 or 4

    const float* Ag = A + (size_t)(m0 + lr) * D_ + lk;
    const float* Wg = W + (size_t)(n0 + lr) * D_ + lk;

    float acc[8][8];
#pragma unroll
    for (int i = 0; i < 8; i++)
#pragma unroll
        for (int j = 0; j < 8; j++) acc[i][j] = 0.f;

    for (int k0 = 0; k0 < D_; k0 += 8) {
        float4 av = *(const float4*)(Ag + k0);
        float4 bv = *(const float4*)(Wg + k0);
        As[lk+0][lr] = av.x; As[lk+1][lr] = av.y;
        As[lk+2][lr] = av.z; As[lk+3][lr] = av.w;
        Bs[lk+0][lr] = bv.x; Bs[lk+1][lr] = bv.y;
        Bs[lk+2][lr] = bv.z; Bs[lk+3][lr] = bv.w;
        __syncthreads();

#pragma unroll
        for (int kk = 0; kk < 8; kk++) {
            float a[8], b[8];
            float4 t0 = *(const float4*)&As[kk][ty*8];
            float4 t1 = *(const float4*)&As[kk][ty*8+4];
            a[0]=t0.x; a[1]=t0.y; a[2]=t0.z; a[3]=t0.w;
            a[4]=t1.x; a[5]=t1.y; a[6]=t1.z; a[7]=t1.w;
            float4 u0 = *(const float4*)&Bs[kk][tx*8];
            float4 u1 = *(const float4*)&Bs[kk][tx*8+4];
            b[0]=u0.x; b[1]=u0.y; b[2]=u0.z; b[3]=u0.w;
            b[4]=u1.x; b[5]=u1.y; b[6]=u1.z; b[7]=u1.w;
#pragma unroll
            for (int i = 0; i < 8; i++)
#pragma unroll
                for (int j = 0; j < 8; j++)
                    acc[i][j] = fmaf(a[i], b[j], acc[i][j]);
        }
        __syncthreads();
    }

#pragma unroll
    for (int i = 0; i < 8; i++) {
        const int row = m0 + ty*8 + i;
        if (MODE == 0) {
            const int b = row >> 11;         // row / S_
            const int s = row & (S_ - 1);
#pragma unroll
            for (int j = 0; j < 8; j += 4) {
                const int col = n0 + tx*8 + j;
                const int h  = col >> 6;
                const int hd = col & 63;
                float4 v = make_float4(acc[i][j], acc[i][j+1], acc[i][j+2], acc[i][j+3]);
                *(float4*)&C[ (size_t)(((b*H_ + h)*S_) + s) * HD_ + hd ] = v;
            }
        } else {
#pragma unroll
            for (int j = 0; j < 8; j += 4) {
                const int col = n0 + tx*8 + j;
                float4 v = make_float4(acc[i][j], acc[i][j+1], acc[i][j+2], acc[i][j+3]);
                *(float4*)&C[ (size_t)row * D_ + col ] = v;
            }
        }
    }
}

// =====================================================================
// def_w[bh, t] = sum_u sigmoid( 0.125 * dot(Qd[bh,t,:], Kd[bh,u,:]) )
// 64 t-rows per block, streaming over u-tiles of 64. 256 threads, 4x4/thread.
// =====================================================================
__global__ __launch_bounds__(256)
void defw_kernel()
{
    __shared__ float Qs[64][64];   // k-major: Qs[k][t_local]
    __shared__ float Ks[64][64];   // k-major: Ks[k][u_local]

    const int tid = threadIdx.x;
    const int tx  = tid & 15;
    const int ty  = tid >> 4;
    const int bh  = blockIdx.y;
    const int t0  = blockIdx.x << 6;

    const int lr  = tid & 63;             // row within tile
    const int lkb = (tid >> 6) << 2;      // 0,4,8,12

    {
        const float* Qg = g_Qd + (size_t)(bh*S_ + t0 + lr) * HD_;
#pragma unroll
        for (int ko = 0; ko < 64; ko += 16) {
            float4 v = *(const float4*)(Qg + ko + lkb);
            Qs[ko+lkb+0][lr] = v.x; Qs[ko+lkb+1][lr] = v.y;
            Qs[ko+lkb+2][lr] = v.z; Qs[ko+lkb+3][lr] = v.w;
        }
    }

    float sums[4] = {0.f, 0.f, 0.f, 0.f};

    for (int u0 = 0; u0 < S_; u0 += 64) {
        __syncthreads();
        const float* Kg = g_Kd + (size_t)(bh*S_ + u0 + lr) * HD_;
#pragma unroll
        for (int ko = 0; ko < 64; ko += 16) {
            float4 v = *(const float4*)(Kg + ko + lkb);
            Ks[ko+lkb+0][lr] = v.x; Ks[ko+lkb+1][lr] = v.y;
            Ks[ko+lkb+2][lr] = v.z; Ks[ko+lkb+3][lr] = v.w;
        }
        __syncthreads();

        float sc[4][4];
#pragma unroll
        for (int i = 0; i < 4; i++)
#pragma unroll
            for (int j = 0; j < 4; j++) sc[i][j] = 0.f;

#pragma unroll 16
        for (int k = 0; k < 64; k++) {
            float4 a = *(const float4*)&Qs[k][ty<<2];
            float4 b = *(const float4*)&Ks[k][tx<<2];
            float ar[4] = {a.x, a.y, a.z, a.w};
            float br[4] = {b.x, b.y, b.z, b.w};
#pragma unroll
            for (int i = 0; i < 4; i++)
#pragma unroll
                for (int j = 0; j < 4; j++)
                    sc[i][j] = fmaf(ar[i], br[j], sc[i][j]);
        }

#pragma unroll
        for (int i = 0; i < 4; i++)
#pragma unroll
            for (int j = 0; j < 4; j++) {
                float x = sc[i][j] * 0.125f;
                sums[i] += __fdividef(1.f, 1.f + __expf(-x));
            }
    }

#pragma unroll
    for (int i = 0; i < 4; i++) {
        float v = sums[i];
        v += __shfl_xor_sync(0xffffffffu, v, 1);
        v += __shfl_xor_sync(0xffffffffu, v, 2);
        v += __shfl_xor_sync(0xffffffffu, v, 4);
        v += __shfl_xor_sync(0xffffffffu, v, 8);
        if (tx == 0) g_defw[bh*S_ + t0 + (ty<<2) + i] = v;
    }
}

// =====================================================================
// Flash attention with per-key defeasible scale:
//   logits[s,t] = 0.125 * (q_s . k_t) * defw[t];  attn = softmax_t; O = attn @ V
// 64 query rows per block, streams key/value tiles of 64.
// Smem: Qs (k-major) + KPs (K tile k-major, reused for P tile r-major) + Vs = 48 KB.
// =====================================================================
__global__ __launch_bounds__(256)
void flash_kernel()
{
    __shared__ float Qs [64][64];   // Qs[k][r]
    __shared__ float KPs[64][64];   // phase 1: K[k][t], phase 2: P[r][t]
    __shared__ float Vs [64][64];   // Vs[t][c]

    const int tid = threadIdx.x;
    const int tx  = tid & 15;
    const int ty  = tid >> 4;
    const int bh  = blockIdx.y;
    const int s0  = blockIdx.x << 6;

    const int lr  = tid & 63;
    const int lkb = (tid >> 6) << 2;

    const int vrow = tid >> 4;          // 0..15
    const int vcol = (tid & 15) << 2;   // 0..60

    {
        const float* Qg = g_Q + (size_t)(bh*S_ + s0 + lr) * HD_;
#pragma unroll
        for (int ko = 0; ko < 64; ko += 16) {
            float4 v = *(const float4*)(Qg + ko + lkb);
            Qs[ko+lkb+0][lr] = v.x; Qs[ko+lkb+1][lr] = v.y;
            Qs[ko+lkb+2][lr] = v.z; Qs[ko+lkb+3][lr] = v.w;
        }
    }

    float o[4][4];
#pragma unroll
    for (int i = 0; i < 4; i++)
#pragma unroll
        for (int j = 0; j < 4; j++) o[i][j] = 0.f;
    float mrow[4] = {-1e30f, -1e30f, -1e30f, -1e30f};
    float lsum[4] = {0.f, 0.f, 0.f, 0.f};

    for (int t0 = 0; t0 < S_; t0 += 64) {
        __syncthreads();   // previous iteration done reading KPs/Vs
        {
            const float* Kg = g_K + (size_t)(bh*S_ + t0 + lr) * HD_;
#pragma unroll
            for (int ko = 0; ko < 64; ko += 16) {
                float4 v = *(const float4*)(Kg + ko + lkb);
                KPs[ko+lkb+0][lr] = v.x; KPs[ko+lkb+1][lr] = v.y;
                KPs[ko+lkb+2][lr] = v.z; KPs[ko+lkb+3][lr] = v.w;
            }
            const float* Vg = g_V + (size_t)(bh*S_ + t0) * HD_;
#pragma unroll
            for (int ro = 0; ro < 64; ro += 16) {
                float4 v = *(const float4*)(Vg + (size_t)(ro + vrow) * HD_ + vcol);
                *(float4*)&Vs[ro + vrow][vcol] = v;
            }
        }
        float dw[4];
#pragma unroll
        for (int j = 0; j < 4; j++)
            dw[j] = 0.125f * g_defw[bh*S_ + t0 + (tx<<2) + j];
        __syncthreads();

        // scores = Q . K^T
        float sc[4][4];
#pragma unroll
        for (int i = 0; i < 4; i++)
#pragma unroll
            for (int j = 0; j < 4; j++) sc[i][j] = 0.f;
#pragma unroll 16
        for (int k = 0; k < 64; k++) {
            float4 a = *(const float4*)&Qs [k][ty<<2];
            float4 b = *(const float4*)&KPs[k][tx<<2];
            float ar[4] = {a.x, a.y, a.z, a.w};
            float br[4] = {b.x, b.y, b.z, b.w};
#pragma unroll
            for (int i = 0; i < 4; i++)
#pragma unroll
                for (int j = 0; j < 4; j++)
                    sc[i][j] = fmaf(ar[i], br[j], sc[i][j]);
        }
#pragma unroll
        for (int i = 0; i < 4; i++)
#pragma unroll
            for (int j = 0; j < 4; j++)
                sc[i][j] *= dw[j];

        // online softmax update
#pragma unroll
        for (int i = 0; i < 4; i++) {
            float rm = fmaxf(fmaxf(sc[i][0], sc[i][1]), fmaxf(sc[i][2], sc[i][3]));
            rm = fmaxf(rm, __shfl_xor_sync(0xffffffffu, rm, 1));
            rm = fmaxf(rm, __shfl_xor_sync(0xffffffffu, rm, 2));
            rm = fmaxf(rm, __shfl_xor_sync(0xffffffffu, rm, 4));
            rm = fmaxf(rm, __shfl_xor_sync(0xffffffffu, rm, 8));
            float newm  = fmaxf(mrow[i], rm);
            float alpha = __expf(mrow[i] - newm);
            float rs = 0.f;
#pragma unroll
            for (int j = 0; j < 4; j++) {
                sc[i][j] = __expf(sc[i][j] - newm);
                rs += sc[i][j];
            }
            rs += __shfl_xor_sync(0xffffffffu, rs, 1);
            rs += __shfl_xor_sync(0xffffffffu, rs, 2);
            rs += __shfl_xor_sync(0xffffffffu, rs, 4);
            rs += __shfl_xor_sync(0xffffffffu, rs, 8);
            lsum[i] = lsum[i] * alpha + rs;
            mrow[i] = newm;
#pragma unroll
            for (int j = 0; j < 4; j++) o[i][j] *= alpha;
        }

        __syncthreads();   // everyone done reading K from KPs
        // write P (r-major) into KPs
        float* KPf = &KPs[0][0];
#pragma unroll
        for (int i = 0; i < 4; i++) {
            float4 v = make_float4(sc[i][0], sc[i][1], sc[i][2], sc[i][3]);
            *(float4*)(KPf + ((ty<<2) + i) * 64 + (tx<<2)) = v;
        }
        __syncthreads();

        // O += P @ V
#pragma unroll 16
        for (int t = 0; t < 64; t++) {
            float4 vv = *(const float4*)&Vs[t][tx<<2];
            float vr[4] = {vv.x, vv.y, vv.z, vv.w};
#pragma unroll
            for (int i = 0; i < 4; i++) {
                float p = KPf[((ty<<2) + i) * 64 + t];
#pragma unroll
                for (int j = 0; j < 4; j++)
                    o[i][j] = fmaf(p, vr[j], o[i][j]);
            }
        }
    }

    // finalize + write attended in (B, S, D) layout
    const int b = bh >> 4;
    const int h = bh & 15;
#pragma unroll
    for (int i = 0; i < 4; i++) {
        const float inv = __fdividef(1.f, lsum[i]);
        const int s = s0 + (ty<<2) + i;
        float4 v = make_float4(o[i][0]*inv, o[i][1]*inv, o[i][2]*inv, o[i][3]*inv);
        *(float4*)&g_att[ (size_t)(b*S_ + s) * D_ + h*HD_ + (tx<<2) ] = v;
    }
}

// =====================================================================
extern "C" void kernel_launch(void* const* d_in, const int* in_sizes, int n_in,
                              void* d_out, int out_size)
{
    const float* qi  = (const float*)d_in[0];
    const float* ki  = (const float*)d_in[1];
    const float* vi  = (const float*)d_in[2];
    const float* Wq  = (const float*)d_in[3];
    const float* Wqd = (const float*)d_in[4];
    const float* Wk  = (const float*)d_in[5];
    const float* Wkd = (const float*)d_in[6];
    const float* Wv  = (const float*)d_in[7];
    const float* Wo  = (const float*)d_in[8];
    float* out = (float*)d_out;

    float *pQ, *pQd, *pK, *pKd, *pV, *pAtt;
    cudaGetSymbolAddress((void**)&pQ,  g_Q);
    cudaGetSymbolAddress((void**)&pQd, g_Qd);
    cudaGetSymbolAddress((void**)&pK,  g_K);
    cudaGetSymbolAddress((void**)&pKd, g_Kd);
    cudaGetSymbolAddress((void**)&pV,  g_V);
    cudaGetSymbolAddress((void**)&pAtt, g_att);

    dim3 blk(256);
    dim3 gg(8, 32);      // 1024/128 n-tiles x 4096/128 m-tiles

    gemm_kernel<0><<<gg, blk>>>(qi, Wq,  pQ);
    gemm_kernel<0><<<gg, blk>>>(qi, Wqd, pQd);
    gemm_kernel<0><<<gg, blk>>>(ki, Wk,  pK);
    gemm_kernel<0><<<gg, blk>>>(ki, Wkd, pKd);
    gemm_kernel<0><<<gg, blk>>>(vi, Wv,  pV);

    defw_kernel <<<dim3(32, 32), blk>>>();
    flash_kernel<<<dim3(32, 32), blk>>>();

    gemm_kernel<1><<<gg, blk>>>(pAtt, Wo, out);
}

// round 5
// speedup vs baseline: 1.1919x; 1.1919x over previous
#include <cuda_runtime.h>
#include <cstdint>

#define B_   2
#define S_   2048
#define D_   1024
#define H_   16
#define HD_  64
#define BH_  (B_*H_)      // 32
#define M_   (B_*S_)      // 4096

// ------------------- scratch (device globals; no allocation) -------------------
__device__ float g_Q  [BH_*S_*HD_];
__device__ float g_Qd [BH_*S_*HD_];
__device__ float g_K  [BH_*S_*HD_];
__device__ float g_Kd [BH_*S_*HD_];
__device__ float g_V  [BH_*S_*HD_];
__device__ float g_defw[BH_*S_];
__device__ float g_att[M_*D_];

// ===================== helpers =====================
__device__ __forceinline__ float tf32_rna(float x) {
    uint32_t o; asm("cvt.rna.tf32.f32 %0, %1;" : "=r"(o) : "f"(x));
    return __uint_as_float(o);
}
// m16n8k8 tf32 MMA (sm_80+, works on base sm_103 target)
__device__ __forceinline__ void mma8(float* c, const uint32_t* a, const uint32_t* b) {
    asm volatile(
        "mma.sync.aligned.m16n8k8.row.col.f32.tf32.tf32.f32 "
        "{%0,%1,%2,%3}, {%4,%5,%6,%7}, {%8,%9}, {%0,%1,%2,%3};"
        : "+f"(c[0]), "+f"(c[1]), "+f"(c[2]), "+f"(c[3])
        : "r"(a[0]), "r"(a[1]), "r"(a[2]), "r"(a[3]), "r"(b[0]), "r"(b[1]));
}

// =====================================================================
// Tensor-core TF32 GEMM: C = A @ W^T.  A: [M_, D_], W: [1024, D_] row-major.
// 128x128 CTA tile, 8 warps (2 m x 4 n), warp tile 64x32 = 4x4 m16n8k8 frags.
// SPLIT=3: 3xTF32 compensation (Ahi*Bhi + Ahi*Blo + Alo*Bhi) ~ fp32 accuracy.
// SPLIT=1: plain tf32 (defeasible path only).
// MODE 0: scatter C[m,n] -> headlayout[(b*H+h)*S+s][hd];  MODE 1: linear.
// =====================================================================
template<int MODE, int SPLIT>
__global__ __launch_bounds__(256)
void mma_gemm(const float* __restrict__ A, const float* __restrict__ W,
              float* __restrict__ C)
{
    constexpr int NS = (SPLIT == 3) ? 2 : 1;      // hi (+ lo)
    __shared__ float As[NS][16][132];             // k-major, +4 pad
    __shared__ float Bs[NS][16][132];

    const int tid  = threadIdx.x;
    const int lane = tid & 31;
    const int warp = tid >> 5;
    const int wm   = warp & 1;       // m offset 64*wm
    const int wn   = warp >> 1;      // n offset 32*wn
    const int m0   = blockIdx.y << 7;
    const int n0   = blockIdx.x << 7;

    float acc[4][4][4];
#pragma unroll
    for (int mt = 0; mt < 4; mt++)
#pragma unroll
        for (int nt = 0; nt < 4; nt++)
#pragma unroll
            for (int q = 0; q < 4; q++) acc[mt][nt][q] = 0.f;

    const int lrow = tid >> 2;         // 0..63
    const int lk   = (tid & 3) << 2;   // 0,4,8,12
    const int fr   = lane >> 2;        // 0..7
    const int fc   = lane & 3;         // 0..3

    for (int k0 = 0; k0 < D_; k0 += 16) {
        // ---- global -> smem (convert to tf32 hi, residual lo) ----
#pragma unroll
        for (int half = 0; half < 2; ++half) {
            const int row = lrow + half * 64;
            float4 av = *(const float4*)(A + (size_t)(m0 + row) * D_ + k0 + lk);
            float4 bv = *(const float4*)(W + (size_t)(n0 + row) * D_ + k0 + lk);
            float aa[4] = {av.x, av.y, av.z, av.w};
            float bb[4] = {bv.x, bv.y, bv.z, bv.w};
#pragma unroll
            for (int i = 0; i < 4; i++) {
                float ah = tf32_rna(aa[i]);
                float bh = tf32_rna(bb[i]);
                As[0][lk + i][row] = ah;
                Bs[0][lk + i][row] = bh;
                if (SPLIT == 3) {
                    As[1][lk + i][row] = aa[i] - ah;
                    Bs[1][lk + i][row] = bb[i] - bh;
                }
            }
        }
        __syncthreads();

#pragma unroll
        for (int ks = 0; ks < 16; ks += 8) {
            uint32_t ahi[4][4], alo[4][4], bhi[4][2], blo[4][2];
#pragma unroll
            for (int mt = 0; mt < 4; mt++) {
                const int mb = wm * 64 + mt * 16 + fr;
                ahi[mt][0] = __float_as_uint(As[0][ks + fc    ][mb    ]);
                ahi[mt][1] = __float_as_uint(As[0][ks + fc    ][mb + 8]);
                ahi[mt][2] = __float_as_uint(As[0][ks + fc + 4][mb    ]);
                ahi[mt][3] = __float_as_uint(As[0][ks + fc + 4][mb + 8]);
                if (SPLIT == 3) {
                    alo[mt][0] = __float_as_uint(As[1][ks + fc    ][mb    ]);
                    alo[mt][1] = __float_as_uint(As[1][ks + fc    ][mb + 8]);
                    alo[mt][2] = __float_as_uint(As[1][ks + fc + 4][mb    ]);
                    alo[mt][3] = __float_as_uint(As[1][ks + fc + 4][mb + 8]);
                }
            }
#pragma unroll
            for (int nt = 0; nt < 4; nt++) {
                const int nb = wn * 32 + nt * 8 + fr;
                bhi[nt][0] = __float_as_uint(Bs[0][ks + fc    ][nb]);
                bhi[nt][1] = __float_as_uint(Bs[0][ks + fc + 4][nb]);
                if (SPLIT == 3) {
                    blo[nt][0] = __float_as_uint(Bs[1][ks + fc    ][nb]);
                    blo[nt][1] = __float_as_uint(Bs[1][ks + fc + 4][nb]);
                }
            }
#pragma unroll
            for (int mt = 0; mt < 4; mt++)
#pragma unroll
                for (int nt = 0; nt < 4; nt++) {
                    mma8(acc[mt][nt], ahi[mt], bhi[nt]);
                    if (SPLIT == 3) {
                        mma8(acc[mt][nt], ahi[mt], blo[nt]);
                        mma8(acc[mt][nt], alo[mt], bhi[nt]);
                    }
                }
        }
        __syncthreads();
    }

    // ---- epilogue: c0,c1 at (row, 2c),(row,2c+1); c2,c3 at row+8 ----
    const int c2 = (lane & 3) << 1;
#pragma unroll
    for (int mt = 0; mt < 4; mt++) {
        const int mrow = m0 + wm * 64 + mt * 16 + fr;
#pragma unroll
        for (int nt = 0; nt < 4; nt++) {
            const int col = wn * 32 + nt * 8 + c2;    // 0..127 within tile
            float* d0;
            float* d1;
            if (MODE == 0) {
                const int b  = mrow >> 11;
                const int s  = mrow & (S_ - 1);
                const int h  = (blockIdx.x << 1) + (wn >> 1);
                const int hd = ((wn & 1) << 5) + nt * 8 + c2;
                float* base0 = C + (size_t)((b * H_ + h) * S_ + s) * HD_ + hd;
                float* base1 = C + (size_t)((b * H_ + h) * S_ + (s + 8)) * HD_ + hd;
                // note: mrow+8 keeps same b (tile rows stay within one batch: S_ multiple of 128)
                d0 = base0; d1 = base1;
            } else {
                d0 = C + (size_t)mrow * D_ + n0 + col;
                d1 = C + (size_t)(mrow + 8) * D_ + n0 + col;
            }
            *(float2*)d0 = make_float2(acc[mt][nt][0], acc[mt][nt][1]);
            *(float2*)d1 = make_float2(acc[mt][nt][2], acc[mt][nt][3]);
        }
    }
}

// =====================================================================
// def_w[bh, t] = sum_u sigmoid( 0.125 * dot(Qd[bh,t,:], Kd[bh,u,:]) )
// =====================================================================
__global__ __launch_bounds__(256)
void defw_kernel()
{
    __shared__ float Qs[64][64];   // k-major
    __shared__ float Ks[64][64];   // k-major

    const int tid = threadIdx.x;
    const int tx  = tid & 15;
    const int ty  = tid >> 4;
    const int bh  = blockIdx.y;
    const int t0  = blockIdx.x << 6;

    const int lr  = tid & 63;
    const int lkb = (tid >> 6) << 2;

    {
        const float* Qg = g_Qd + (size_t)(bh*S_ + t0 + lr) * HD_;
#pragma unroll
        for (int ko = 0; ko < 64; ko += 16) {
            float4 v = *(const float4*)(Qg + ko + lkb);
            Qs[ko+lkb+0][lr] = v.x; Qs[ko+lkb+1][lr] = v.y;
            Qs[ko+lkb+2][lr] = v.z; Qs[ko+lkb+3][lr] = v.w;
        }
    }

    float sums[4] = {0.f, 0.f, 0.f, 0.f};

    for (int u0 = 0; u0 < S_; u0 += 64) {
        __syncthreads();
        const float* Kg = g_Kd + (size_t)(bh*S_ + u0 + lr) * HD_;
#pragma unroll
        for (int ko = 0; ko < 64; ko += 16) {
            float4 v = *(const float4*)(Kg + ko + lkb);
            Ks[ko+lkb+0][lr] = v.x; Ks[ko+lkb+1][lr] = v.y;
            Ks[ko+lkb+2][lr] = v.z; Ks[ko+lkb+3][lr] = v.w;
        }
        __syncthreads();

        float sc[4][4];
#pragma unroll
        for (int i = 0; i < 4; i++)
#pragma unroll
            for (int j = 0; j < 4; j++) sc[i][j] = 0.f;

#pragma unroll 16
        for (int k = 0; k < 64; k++) {
            float4 a = *(const float4*)&Qs[k][ty<<2];
            float4 b = *(const float4*)&Ks[k][tx<<2];
            float ar[4] = {a.x, a.y, a.z, a.w};
            float br[4] = {b.x, b.y, b.z, b.w};
#pragma unroll
            for (int i = 0; i < 4; i++)
#pragma unroll
                for (int j = 0; j < 4; j++)
                    sc[i][j] = fmaf(ar[i], br[j], sc[i][j]);
        }

#pragma unroll
        for (int i = 0; i < 4; i++)
#pragma unroll
            for (int j = 0; j < 4; j++) {
                float x = sc[i][j] * 0.125f;
                sums[i] += __fdividef(1.f, 1.f + __expf(-x));
            }
    }

#pragma unroll
    for (int i = 0; i < 4; i++) {
        float v = sums[i];
        v += __shfl_xor_sync(0xffffffffu, v, 1);
        v += __shfl_xor_sync(0xffffffffu, v, 2);
        v += __shfl_xor_sync(0xffffffffu, v, 4);
        v += __shfl_xor_sync(0xffffffffu, v, 8);
        if (tx == 0) g_defw[bh*S_ + t0 + (ty<<2) + i] = v;
    }
}

// =====================================================================
// Flash attention with per-key defeasible scale.
// =====================================================================
__global__ __launch_bounds__(256)
void flash_kernel()
{
    __shared__ float Qs [64][64];
    __shared__ float KPs[64][64];
    __shared__ float Vs [64][64];

    const int tid = threadIdx.x;
    const int tx  = tid & 15;
    const int ty  = tid >> 4;
    const int bh  = blockIdx.y;
    const int s0  = blockIdx.x << 6;

    const int lr  = tid & 63;
    const int lkb = (tid >> 6) << 2;

    const int vrow = tid >> 4;
    const int vcol = (tid & 15) << 2;

    {
        const float* Qg = g_Q + (size_t)(bh*S_ + s0 + lr) * HD_;
#pragma unroll
        for (int ko = 0; ko < 64; ko += 16) {
            float4 v = *(const float4*)(Qg + ko + lkb);
            Qs[ko+lkb+0][lr] = v.x; Qs[ko+lkb+1][lr] = v.y;
            Qs[ko+lkb+2][lr] = v.z; Qs[ko+lkb+3][lr] = v.w;
        }
    }

    float o[4][4];
#pragma unroll
    for (int i = 0; i < 4; i++)
#pragma unroll
        for (int j = 0; j < 4; j++) o[i][j] = 0.f;
    float mrow[4] = {-1e30f, -1e30f, -1e30f, -1e30f};
    float lsum[4] = {0.f, 0.f, 0.f, 0.f};

    for (int t0 = 0; t0 < S_; t0 += 64) {
        __syncthreads();
        {
            const float* Kg = g_K + (size_t)(bh*S_ + t0 + lr) * HD_;
#pragma unroll
            for (int ko = 0; ko < 64; ko += 16) {
                float4 v = *(const float4*)(Kg + ko + lkb);
                KPs[ko+lkb+0][lr] = v.x; KPs[ko+lkb+1][lr] = v.y;
                KPs[ko+lkb+2][lr] = v.z; KPs[ko+lkb+3][lr] = v.w;
            }
            const float* Vg = g_V + (size_t)(bh*S_ + t0) * HD_;
#pragma unroll
            for (int ro = 0; ro < 64; ro += 16) {
                float4 v = *(const float4*)(Vg + (size_t)(ro + vrow) * HD_ + vcol);
                *(float4*)&Vs[ro + vrow][vcol] = v;
            }
        }
        float dw[4];
#pragma unroll
        for (int j = 0; j < 4; j++)
            dw[j] = 0.125f * g_defw[bh*S_ + t0 + (tx<<2) + j];
        __syncthreads();

        float sc[4][4];
#pragma unroll
        for (int i = 0; i < 4; i++)
#pragma unroll
            for (int j = 0; j < 4; j++) sc[i][j] = 0.f;
#pragma unroll 16
        for (int k = 0; k < 64; k++) {
            float4 a = *(const float4*)&Qs [k][ty<<2];
            float4 b = *(const float4*)&KPs[k][tx<<2];
            float ar[4] = {a.x, a.y, a.z, a.w};
            float br[4] = {b.x, b.y, b.z, b.w};
#pragma unroll
            for (int i = 0; i < 4; i++)
#pragma unroll
                for (int j = 0; j < 4; j++)
                    sc[i][j] = fmaf(ar[i], br[j], sc[i][j]);
        }
#pragma unroll
        for (int i = 0; i < 4; i++)
#pragma unroll
            for (int j = 0; j < 4; j++)
                sc[i][j] *= dw[j];

#pragma unroll
        for (int i = 0; i < 4; i++) {
            float rm = fmaxf(fmaxf(sc[i][0], sc[i][1]), fmaxf(sc[i][2], sc[i][3]));
            rm = fmaxf(rm, __shfl_xor_sync(0xffffffffu, rm, 1));
            rm = fmaxf(rm, __shfl_xor_sync(0xffffffffu, rm, 2));
            rm = fmaxf(rm, __shfl_xor_sync(0xffffffffu, rm, 4));
            rm = fmaxf(rm, __shfl_xor_sync(0xffffffffu, rm, 8));
            float newm  = fmaxf(mrow[i], rm);
            float alpha = __expf(mrow[i] - newm);
            float rs = 0.f;
#pragma unroll
            for (int j = 0; j < 4; j++) {
                sc[i][j] = __expf(sc[i][j] - newm);
                rs += sc[i][j];
            }
            rs += __shfl_xor_sync(0xffffffffu, rs, 1);
            rs += __shfl_xor_sync(0xffffffffu, rs, 2);
            rs += __shfl_xor_sync(0xffffffffu, rs, 4);
            rs += __shfl_xor_sync(0xffffffffu, rs, 8);
            lsum[i] = lsum[i] * alpha + rs;
            mrow[i] = newm;
#pragma unroll
            for (int j = 0; j < 4; j++) o[i][j] *= alpha;
        }

        __syncthreads();
        float* KPf = &KPs[0][0];
#pragma unroll
        for (int i = 0; i < 4; i++) {
            float4 v = make_float4(sc[i][0], sc[i][1], sc[i][2], sc[i][3]);
            *(float4*)(KPf + ((ty<<2) + i) * 64 + (tx<<2)) = v;
        }
        __syncthreads();

#pragma unroll 16
        for (int t = 0; t < 64; t++) {
            float4 vv = *(const float4*)&Vs[t][tx<<2];
            float vr[4] = {vv.x, vv.y, vv.z, vv.w};
#pragma unroll
            for (int i = 0; i < 4; i++) {
                float p = KPf[((ty<<2) + i) * 64 + t];
#pragma unroll
                for (int j = 0; j < 4; j++)
                    o[i][j] = fmaf(p, vr[j], o[i][j]);
            }
        }
    }

    const int b = bh >> 4;
    const int h = bh & 15;
#pragma unroll
    for (int i = 0; i < 4; i++) {
        const float inv = __fdividef(1.f, lsum[i]);
        const int s = s0 + (ty<<2) + i;
        float4 v = make_float4(o[i][0]*inv, o[i][1]*inv, o[i][2]*inv, o[i][3]*inv);
        *(float4*)&g_att[ (size_t)(b*S_ + s) * D_ + h*HD_ + (tx<<2) ] = v;
    }
}

// =====================================================================
extern "C" void kernel_launch(void* const* d_in, const int* in_sizes, int n_in,
                              void* d_out, int out_size)
{
    const float* qi  = (const float*)d_in[0];
    const float* ki  = (const float*)d_in[1];
    const float* vi  = (const float*)d_in[2];
    const float* Wq  = (const float*)d_in[3];
    const float* Wqd = (const float*)d_in[4];
    const float* Wk  = (const float*)d_in[5];
    const float* Wkd = (const float*)d_in[6];
    const float* Wv  = (const float*)d_in[7];
    const float* Wo  = (const float*)d_in[8];
    float* out = (float*)d_out;

    float *pQ, *pQd, *pK, *pKd, *pV, *pAtt;
    cudaGetSymbolAddress((void**)&pQ,  g_Q);
    cudaGetSymbolAddress((void**)&pQd, g_Qd);
    cudaGetSymbolAddress((void**)&pK,  g_K);
    cudaGetSymbolAddress((void**)&pKd, g_Kd);
    cudaGetSymbolAddress((void**)&pV,  g_V);
    cudaGetSymbolAddress((void**)&pAtt, g_att);

    dim3 blk(256);
    dim3 gg(8, 32);      // 1024/128 n-tiles x 4096/128 m-tiles

    mma_gemm<0,3><<<gg, blk>>>(qi, Wq,  pQ);
    mma_gemm<0,1><<<gg, blk>>>(qi, Wqd, pQd);
    mma_gemm<0,3><<<gg, blk>>>(ki, Wk,  pK);
    mma_gemm<0,1><<<gg, blk>>>(ki, Wkd, pKd);
    mma_gemm<0,3><<<gg, blk>>>(vi, Wv,  pV);

    defw_kernel <<<dim3(32, 32), blk>>>();
    flash_kernel<<<dim3(32, 32), blk>>>();

    mma_gemm<1,3><<<gg, blk>>>(pAtt, Wo, out);
}

// round 6
// speedup vs baseline: 1.5895x; 1.3336x over previous
#include <cuda_runtime.h>
#include <cstdint>

#define B_   2
#define S_   2048
#define D_   1024
#define H_   16
#define HD_  64
#define BH_  (B_*H_)      // 32
#define M_   (B_*S_)      // 4096

// ------------------- scratch (device globals; no allocation) -------------------
__device__ float g_Q  [BH_*S_*HD_];
__device__ float g_Qd [BH_*S_*HD_];
__device__ float g_K  [BH_*S_*HD_];
__device__ float g_Kd [BH_*S_*HD_];
__device__ float g_V  [BH_*S_*HD_];
__device__ float g_defw[BH_*S_];
__device__ float g_att[M_*D_];

// ===================== helpers =====================
__device__ __forceinline__ float tf32_rna(float x) {
    uint32_t o; asm("cvt.rna.tf32.f32 %0, %1;" : "=r"(o) : "f"(x));
    return __uint_as_float(o);
}
__device__ __forceinline__ uint32_t tf32_u(float x) {
    uint32_t o; asm("cvt.rna.tf32.f32 %0, %1;" : "=r"(o) : "f"(x));
    return o;
}
__device__ __forceinline__ uint32_t lo_u(float x, uint32_t hi) {
    return __float_as_uint(x - __uint_as_float(hi));
}
// m16n8k8 tf32 MMA (sm_80+, base sm_103 OK)
__device__ __forceinline__ void mma8(float* c, const uint32_t* a, const uint32_t* b) {
    asm volatile(
        "mma.sync.aligned.m16n8k8.row.col.f32.tf32.tf32.f32 "
        "{%0,%1,%2,%3}, {%4,%5,%6,%7}, {%8,%9}, {%0,%1,%2,%3};"
        : "+f"(c[0]), "+f"(c[1]), "+f"(c[2]), "+f"(c[3])
        : "r"(a[0]), "r"(a[1]), "r"(a[2]), "r"(a[3]), "r"(b[0]), "r"(b[1]));
}

// =====================================================================
// Tensor-core 3xTF32 GEMM: C = A @ W^T. A:[M_,D_], W:[1024,D_] row-major.
// 128x128 CTA tile, 8 warps (2m x 4n), warp 64x32 = 4x4 m16n8k8 frags.
// Raw fp32 in smem (pad 20 -> conflict-free frags), convert-on-read hi/lo,
// double-buffered 16-wide k slabs (one __syncthreads per slab).
// MODE 0: scatter to head layout;  MODE 1: linear.
// =====================================================================
template<int MODE>
__global__ __launch_bounds__(256, 2)
void mma_gemm(const float* __restrict__ A, const float* __restrict__ W,
              float* __restrict__ C)
{
    __shared__ float As[2][128][20];
    __shared__ float Bs[2][128][20];

    const int tid  = threadIdx.x;
    const int lane = tid & 31;
    const int warp = tid >> 5;
    const int wm   = warp & 1;
    const int wn   = warp >> 1;
    const int fr   = lane >> 2;
    const int fc   = lane & 3;
    const int m0   = blockIdx.y << 7;
    const int n0   = blockIdx.x << 7;

    const int lr = tid >> 2;          // 0..63
    const int lc = (tid & 3) << 2;    // 0,4,8,12

    const float* Ag = A + (size_t)(m0 + lr) * D_ + lc;
    const float* Wg = W + (size_t)(n0 + lr) * D_ + lc;

    float acc[4][4][4];
#pragma unroll
    for (int mt = 0; mt < 4; mt++)
#pragma unroll
        for (int nt = 0; nt < 4; nt++)
#pragma unroll
            for (int q = 0; q < 4; q++) acc[mt][nt][q] = 0.f;

    float4 sa0 = *(const float4*)(Ag);
    float4 sa1 = *(const float4*)(Ag + (size_t)64 * D_);
    float4 sb0 = *(const float4*)(Wg);
    float4 sb1 = *(const float4*)(Wg + (size_t)64 * D_);
    *(float4*)&As[0][lr     ][lc] = sa0;
    *(float4*)&As[0][lr + 64][lc] = sa1;
    *(float4*)&Bs[0][lr     ][lc] = sb0;
    *(float4*)&Bs[0][lr + 64][lc] = sb1;
    __syncthreads();

    for (int it = 0; it < 64; ++it) {
        const int cur = it & 1;
        if (it < 63) {
            const int k0 = (it + 1) << 4;
            sa0 = *(const float4*)(Ag + k0);
            sa1 = *(const float4*)(Ag + (size_t)64 * D_ + k0);
            sb0 = *(const float4*)(Wg + k0);
            sb1 = *(const float4*)(Wg + (size_t)64 * D_ + k0);
        }
        const float (*Ab)[20] = As[cur];
        const float (*Bb)[20] = Bs[cur];
#pragma unroll
        for (int ks = 0; ks < 16; ks += 8) {
            uint32_t ahi[4][4], alo[4][4], bhi[4][2], blo[4][2];
#pragma unroll
            for (int mt = 0; mt < 4; mt++) {
                const int mrow = wm * 64 + mt * 16 + fr;
                float r0 = Ab[mrow    ][ks + fc];
                float r1 = Ab[mrow + 8][ks + fc];
                float r2 = Ab[mrow    ][ks + fc + 4];
                float r3 = Ab[mrow + 8][ks + fc + 4];
                ahi[mt][0] = tf32_u(r0); alo[mt][0] = lo_u(r0, ahi[mt][0]);
                ahi[mt][1] = tf32_u(r1); alo[mt][1] = lo_u(r1, ahi[mt][1]);
                ahi[mt][2] = tf32_u(r2); alo[mt][2] = lo_u(r2, ahi[mt][2]);
                ahi[mt][3] = tf32_u(r3); alo[mt][3] = lo_u(r3, ahi[mt][3]);
            }
#pragma unroll
            for (int nt = 0; nt < 4; nt++) {
                const int nrow = wn * 32 + nt * 8 + fr;
                float b0 = Bb[nrow][ks + fc];
                float b1 = Bb[nrow][ks + fc + 4];
                bhi[nt][0] = tf32_u(b0); blo[nt][0] = lo_u(b0, bhi[nt][0]);
                bhi[nt][1] = tf32_u(b1); blo[nt][1] = lo_u(b1, bhi[nt][1]);
            }
#pragma unroll
            for (int mt = 0; mt < 4; mt++)
#pragma unroll
                for (int nt = 0; nt < 4; nt++) {
                    mma8(acc[mt][nt], ahi[mt], bhi[nt]);
                    mma8(acc[mt][nt], ahi[mt], blo[nt]);
                    mma8(acc[mt][nt], alo[mt], bhi[nt]);
                }
        }
        if (it < 63) {
            const int nxt = cur ^ 1;
            *(float4*)&As[nxt][lr     ][lc] = sa0;
            *(float4*)&As[nxt][lr + 64][lc] = sa1;
            *(float4*)&Bs[nxt][lr     ][lc] = sb0;
            *(float4*)&Bs[nxt][lr + 64][lc] = sb1;
        }
        __syncthreads();
    }

    // ---- epilogue (layout identical to R4, verified) ----
    const int c2 = (lane & 3) << 1;
#pragma unroll
    for (int mt = 0; mt < 4; mt++) {
        const int mrow = m0 + wm * 64 + mt * 16 + fr;
#pragma unroll
        for (int nt = 0; nt < 4; nt++) {
            const int col = wn * 32 + nt * 8 + c2;
            float *d0, *d1;
            if (MODE == 0) {
                const int b  = mrow >> 11;
                const int s  = mrow & (S_ - 1);
                const int h  = (blockIdx.x << 1) + (wn >> 1);
                const int hd = ((wn & 1) << 5) + nt * 8 + c2;
                d0 = C + (size_t)((b * H_ + h) * S_ + s) * HD_ + hd;
                d1 = C + (size_t)((b * H_ + h) * S_ + (s + 8)) * HD_ + hd;
            } else {
                d0 = C + (size_t)mrow * D_ + n0 + col;
                d1 = C + (size_t)(mrow + 8) * D_ + n0 + col;
            }
            *(float2*)d0 = make_float2(acc[mt][nt][0], acc[mt][nt][1]);
            *(float2*)d1 = make_float2(acc[mt][nt][2], acc[mt][nt][3]);
        }
    }
}

// =====================================================================
// Tensor defw: def_w[bh,t] = sum_u sigmoid(0.125 * qd[t].kd[u])
// CTA = 64 t-rows, 4 warps x 16 rows, u tiles of 64, QK in 3xTF32.
// Natural row-major tiles, pad 68 -> conflict-free fragment loads.
// =====================================================================
__global__ __launch_bounds__(128)
void defw_kernel()
{
    __shared__ float Qs[64 * 68];
    __shared__ float Ks[64 * 68];

    const int tid  = threadIdx.x;
    const int lane = tid & 31;
    const int warp = tid >> 5;
    const int fr   = lane >> 2;
    const int fc   = lane & 3;
    const int bh   = blockIdx.y;
    const int t0   = blockIdx.x << 6;
    const int wr   = warp << 4;

    {
        const float* Qg = g_Qd + ((size_t)bh * S_ + t0) * HD_;
#pragma unroll
        for (int i = 0; i < 8; i++) {
            int e = i * 128 + tid;
            int row = e >> 4, c4 = (e & 15) << 2;
            *(float4*)&Qs[row * 68 + c4] = *(const float4*)(Qg + (size_t)row * HD_ + c4);
        }
    }

    float s0 = 0.f, s1 = 0.f;

    for (int u0 = 0; u0 < S_; u0 += 64) {
        __syncthreads();
        {
            const float* Kg = g_Kd + ((size_t)bh * S_ + u0) * HD_;
#pragma unroll
            for (int i = 0; i < 8; i++) {
                int e = i * 128 + tid;
                int row = e >> 4, c4 = (e & 15) << 2;
                *(float4*)&Ks[row * 68 + c4] = *(const float4*)(Kg + (size_t)row * HD_ + c4);
            }
        }
        __syncthreads();

        float qk[8][4];
#pragma unroll
        for (int nf = 0; nf < 8; nf++)
#pragma unroll
            for (int q = 0; q < 4; q++) qk[nf][q] = 0.f;

#pragma unroll
        for (int ks = 0; ks < 64; ks += 8) {
            const int ai = (wr + fr) * 68 + ks + fc;
            float r0 = Qs[ai], r1 = Qs[ai + 8 * 68], r2 = Qs[ai + 4], r3 = Qs[ai + 8 * 68 + 4];
            uint32_t ah[4] = {tf32_u(r0), tf32_u(r1), tf32_u(r2), tf32_u(r3)};
            uint32_t al[4] = {lo_u(r0, ah[0]), lo_u(r1, ah[1]), lo_u(r2, ah[2]), lo_u(r3, ah[3])};
#pragma unroll
            for (int nf = 0; nf < 8; nf++) {
                const int bi = (nf * 8 + fr) * 68 + ks + fc;
                float b0 = Ks[bi], b1 = Ks[bi + 4];
                uint32_t bh2[2] = {tf32_u(b0), tf32_u(b1)};
                uint32_t bl2[2] = {lo_u(b0, bh2[0]), lo_u(b1, bh2[1])};
                mma8(qk[nf], ah, bh2);
                mma8(qk[nf], ah, bl2);
                mma8(qk[nf], al, bh2);
            }
        }
#pragma unroll
        for (int nf = 0; nf < 8; nf++) {
            s0 += __fdividef(1.f, 1.f + __expf(-0.125f * qk[nf][0]));
            s0 += __fdividef(1.f, 1.f + __expf(-0.125f * qk[nf][1]));
            s1 += __fdividef(1.f, 1.f + __expf(-0.125f * qk[nf][2]));
            s1 += __fdividef(1.f, 1.f + __expf(-0.125f * qk[nf][3]));
        }
    }

    s0 += __shfl_xor_sync(0xffffffffu, s0, 1);
    s0 += __shfl_xor_sync(0xffffffffu, s0, 2);
    s1 += __shfl_xor_sync(0xffffffffu, s1, 1);
    s1 += __shfl_xor_sync(0xffffffffu, s1, 2);
    if (fc == 0) {
        g_defw[bh * S_ + t0 + wr + fr    ] = s0;
        g_defw[bh * S_ + t0 + wr + fr + 8] = s1;
    }
}

// =====================================================================
// Tensor flash attention: logits = 0.125*(q.k)*defw[t], online softmax,
// O = P@V.  CTA = 64 queries, 4 warps x 16 rows, key tiles of 64.
// QK: 3xTF32.  PV: 2-term (P.Vhi + P.Vlo) -- V rounding is the error
// term that matters under the near-argmax softmax.
// =====================================================================
__global__ __launch_bounds__(128)
void flash_kernel()
{
    extern __shared__ float sm[];
    float* Qs  = sm;                // [64][68]
    float* Ks  = sm + 64 * 68;
    float* Vs  = sm + 2 * 64 * 68;
    float* Ps  = sm + 3 * 64 * 68;
    float* dws = sm + 4 * 64 * 68;  // [64]

    const int tid  = threadIdx.x;
    const int lane = tid & 31;
    const int warp = tid >> 5;
    const int fr   = lane >> 2;
    const int fc   = lane & 3;
    const int bh   = blockIdx.y;
    const int s0   = blockIdx.x << 6;
    const int wr   = warp << 4;

    {
        const float* Qg = g_Q + ((size_t)bh * S_ + s0) * HD_;
#pragma unroll
        for (int i = 0; i < 8; i++) {
            int e = i * 128 + tid;
            int row = e >> 4, c4 = (e & 15) << 2;
            *(float4*)&Qs[row * 68 + c4] = *(const float4*)(Qg + (size_t)row * HD_ + c4);
        }
    }

    float o[8][4];
#pragma unroll
    for (int nf = 0; nf < 8; nf++)
#pragma unroll
        for (int q = 0; q < 4; q++) o[nf][q] = 0.f;
    float mr0 = -1e30f, mr1 = -1e30f, ls0 = 0.f, ls1 = 0.f;

    for (int t0 = 0; t0 < S_; t0 += 64) {
        __syncthreads();
        {
            const float* Kg = g_K + ((size_t)bh * S_ + t0) * HD_;
            const float* Vg = g_V + ((size_t)bh * S_ + t0) * HD_;
#pragma unroll
            for (int i = 0; i < 8; i++) {
                int e = i * 128 + tid;
                int row = e >> 4, c4 = (e & 15) << 2;
                *(float4*)&Ks[row * 68 + c4] = *(const float4*)(Kg + (size_t)row * HD_ + c4);
                *(float4*)&Vs[row * 68 + c4] = *(const float4*)(Vg + (size_t)row * HD_ + c4);
            }
            if (tid < 64) dws[tid] = 0.125f * g_defw[bh * S_ + t0 + tid];
        }
        __syncthreads();

        // ---- QK (3xTF32) ----
        float qk[8][4];
#pragma unroll
        for (int nf = 0; nf < 8; nf++)
#pragma unroll
            for (int q = 0; q < 4; q++) qk[nf][q] = 0.f;

#pragma unroll
        for (int ks = 0; ks < 64; ks += 8) {
            const int ai = (wr + fr) * 68 + ks + fc;
            float r0 = Qs[ai], r1 = Qs[ai + 8 * 68], r2 = Qs[ai + 4], r3 = Qs[ai + 8 * 68 + 4];
            uint32_t ah[4] = {tf32_u(r0), tf32_u(r1), tf32_u(r2), tf32_u(r3)};
            uint32_t al[4] = {lo_u(r0, ah[0]), lo_u(r1, ah[1]), lo_u(r2, ah[2]), lo_u(r3, ah[3])};
#pragma unroll
            for (int nf = 0; nf < 8; nf++) {
                const int bi = (nf * 8 + fr) * 68 + ks + fc;
                float b0 = Ks[bi], b1 = Ks[bi + 4];
                uint32_t bh2[2] = {tf32_u(b0), tf32_u(b1)};
                uint32_t bl2[2] = {lo_u(b0, bh2[0]), lo_u(b1, bh2[1])};
                mma8(qk[nf], ah, bh2);
                mma8(qk[nf], ah, bl2);
                mma8(qk[nf], al, bh2);
            }
        }

        // ---- logits + online softmax ----
        float nm0 = mr0, nm1 = mr1;
#pragma unroll
        for (int nf = 0; nf < 8; nf++) {
            float dw0 = dws[nf * 8 + 2 * fc];
            float dw1 = dws[nf * 8 + 2 * fc + 1];
            qk[nf][0] *= dw0; qk[nf][1] *= dw1;
            qk[nf][2] *= dw0; qk[nf][3] *= dw1;
            nm0 = fmaxf(nm0, fmaxf(qk[nf][0], qk[nf][1]));
            nm1 = fmaxf(nm1, fmaxf(qk[nf][2], qk[nf][3]));
        }
        nm0 = fmaxf(nm0, __shfl_xor_sync(0xffffffffu, nm0, 1));
        nm0 = fmaxf(nm0, __shfl_xor_sync(0xffffffffu, nm0, 2));
        nm1 = fmaxf(nm1, __shfl_xor_sync(0xffffffffu, nm1, 1));
        nm1 = fmaxf(nm1, __shfl_xor_sync(0xffffffffu, nm1, 2));
        const float al0 = __expf(mr0 - nm0);
        const float al1 = __expf(mr1 - nm1);
        mr0 = nm0; mr1 = nm1;

        float rs0 = 0.f, rs1 = 0.f;
#pragma unroll
        for (int nf = 0; nf < 8; nf++) {
            float p0 = tf32_rna(__expf(qk[nf][0] - nm0));
            float p1 = tf32_rna(__expf(qk[nf][1] - nm0));
            float p2 = tf32_rna(__expf(qk[nf][2] - nm1));
            float p3 = tf32_rna(__expf(qk[nf][3] - nm1));
            rs0 += p0 + p1; rs1 += p2 + p3;
            *(float2*)&Ps[(wr + fr    ) * 68 + nf * 8 + 2 * fc] = make_float2(p0, p1);
            *(float2*)&Ps[(wr + fr + 8) * 68 + nf * 8 + 2 * fc] = make_float2(p2, p3);
        }
        rs0 += __shfl_xor_sync(0xffffffffu, rs0, 1);
        rs0 += __shfl_xor_sync(0xffffffffu, rs0, 2);
        rs1 += __shfl_xor_sync(0xffffffffu, rs1, 1);
        rs1 += __shfl_xor_sync(0xffffffffu, rs1, 2);
        ls0 = ls0 * al0 + rs0;
        ls1 = ls1 * al1 + rs1;
#pragma unroll
        for (int nf = 0; nf < 8; nf++) {
            o[nf][0] *= al0; o[nf][1] *= al0;
            o[nf][2] *= al1; o[nf][3] *= al1;
        }
        __syncwarp();

        // ---- PV: O += P @ V  (V split hi/lo) ----
#pragma unroll
        for (int ks = 0; ks < 64; ks += 8) {
            const int ai = (wr + fr) * 68 + ks + fc;
            uint32_t pa[4] = {
                __float_as_uint(Ps[ai]),
                __float_as_uint(Ps[ai + 8 * 68]),
                __float_as_uint(Ps[ai + 4]),
                __float_as_uint(Ps[ai + 8 * 68 + 4])};
#pragma unroll
            for (int nf = 0; nf < 8; nf++) {
                const int bi = (ks + fc) * 68 + nf * 8 + fr;
                float b0 = Vs[bi], b1 = Vs[bi + 4 * 68];
                uint32_t vh[2] = {tf32_u(b0), tf32_u(b1)};
                uint32_t vl[2] = {lo_u(b0, vh[0]), lo_u(b1, vh[1])};
                mma8(o[nf], pa, vh);
                mma8(o[nf], pa, vl);
            }
        }
    }

    const float inv0 = __fdividef(1.f, ls0);
    const float inv1 = __fdividef(1.f, ls1);
    const int b = bh >> 4, h = bh & 15;
    float* base0 = g_att + (size_t)(b * S_ + s0 + wr + fr) * D_ + h * HD_;
    float* base1 = base0 + (size_t)8 * D_;
#pragma unroll
    for (int nf = 0; nf < 8; nf++) {
        *(float2*)(base0 + nf * 8 + 2 * fc) = make_float2(o[nf][0] * inv0, o[nf][1] * inv0);
        *(float2*)(base1 + nf * 8 + 2 * fc) = make_float2(o[nf][2] * inv1, o[nf][3] * inv1);
    }
}

// =====================================================================
extern "C" void kernel_launch(void* const* d_in, const int* in_sizes, int n_in,
                              void* d_out, int out_size)
{
    const float* qi  = (const float*)d_in[0];
    const float* ki  = (const float*)d_in[1];
    const float* vi  = (const float*)d_in[2];
    const float* Wq  = (const float*)d_in[3];
    const float* Wqd = (const float*)d_in[4];
    const float* Wk  = (const float*)d_in[5];
    const float* Wkd = (const float*)d_in[6];
    const float* Wv  = (const float*)d_in[7];
    const float* Wo  = (const float*)d_in[8];
    float* out = (float*)d_out;

    float *pQ, *pQd, *pK, *pKd, *pV, *pAtt;
    cudaGetSymbolAddress((void**)&pQ,  g_Q);
    cudaGetSymbolAddress((void**)&pQd, g_Qd);
    cudaGetSymbolAddress((void**)&pK,  g_K);
    cudaGetSymbolAddress((void**)&pKd, g_Kd);
    cudaGetSymbolAddress((void**)&pV,  g_V);
    cudaGetSymbolAddress((void**)&pAtt, g_att);

    const int FLASH_SMEM = (4 * 64 * 68 + 64) * 4;   // 69888 B
    static int configured = 0;
    if (!configured) {
        cudaFuncSetAttribute(flash_kernel, cudaFuncAttributeMaxDynamicSharedMemorySize, FLASH_SMEM);
        configured = 1;
    }

    dim3 blk(256);
    dim3 gg(8, 32);      // 1024/128 n-tiles x 4096/128 m-tiles

    mma_gemm<0><<<gg, blk>>>(qi, Wq,  pQ);
    mma_gemm<0><<<gg, blk>>>(qi, Wqd, pQd);
    mma_gemm<0><<<gg, blk>>>(ki, Wk,  pK);
    mma_gemm<0><<<gg, blk>>>(ki, Wkd, pKd);
    mma_gemm<0><<<gg, blk>>>(vi, Wv,  pV);

    defw_kernel <<<dim3(32, 32), dim3(128)>>>();
    flash_kernel<<<dim3(32, 32), dim3(128), FLASH_SMEM>>>();

    mma_gemm<1><<<gg, blk>>>(pAtt, Wo, out);
}